// round 8
// baseline (speedup 1.0000x reference)
#include <cuda_runtime.h>
#include <cuda_fp16.h>
#include <stdint.h>
#include <math.h>

// ---------------------------------------------------------------------------
// EncoderLayer: B=32, S=512, D=1024, H=16, dk=64, F=4096
// Round 7 (= Round 6 resubmit; infra died): fp16 m16n8k16 warp-MMA GEMMs
// (fp32 accum), fp16 operands staged in global scratch (one-time
// cvt/transpose per launch), cp.async 4-stage. Attention + LN fp32
// (attention emits fp16 ctx for the Wo GEMM).
// ---------------------------------------------------------------------------

#define B_  32
#define S_  512
#define D_  1024
#define H_  16
#define DK_ 64
#define F_  4096
#define M_  (B_ * S_)          // 16384 rows

// -------------------- scratch (device globals; no allocs) ------------------
__device__ float  g_q   [M_ * D_];
__device__ float  g_k   [M_ * D_];
__device__ float  g_v   [M_ * D_];
__device__ float  g_attn[M_ * D_];
__device__ float  g_out1[M_ * D_];
__device__ float  g_ffn [M_ * D_];

__device__ __half g_xh  [M_ * D_];
__device__ __half g_ctxh[M_ * D_];
__device__ __half g_o1h [M_ * D_];
__device__ __half g_hbh [M_ * F_];
__device__ __half g_wqh [D_ * D_];
__device__ __half g_wkh [D_ * D_];
__device__ __half g_wvh [D_ * D_];
__device__ __half g_woh [D_ * D_];
__device__ __half g_w1t [F_ * D_];   // [n=F][k=D]
__device__ __half g_w2t [D_ * F_];   // [n=D][k=F]

// ---------------------------------------------------------------------------
// Helpers
// ---------------------------------------------------------------------------
__device__ __forceinline__ float gelu_erf_f(float x) {
    return 0.5f * x * (1.0f + erff(x * 0.70710678118654752f));
}
__device__ __forceinline__ uint32_t smem_u32(const void* p) {
    uint32_t a;
    asm("{ .reg .u64 t; cvta.to.shared.u64 t, %1; cvt.u32.u64 %0, t; }"
        : "=r"(a) : "l"(p));
    return a;
}
__device__ __forceinline__ void cp16(uint32_t s, const void* g) {
    asm volatile("cp.async.cg.shared.global [%0], [%1], 16;" :: "r"(s), "l"(g));
}
__device__ __forceinline__ void cp_commit() {
    asm volatile("cp.async.commit_group;" ::: "memory");
}
template <int N>
__device__ __forceinline__ void cp_wait() {
    asm volatile("cp.async.wait_group %0;" :: "n"(N) : "memory");
}
__device__ __forceinline__ void mma_f16(float c[4], const uint32_t a[4],
                                        const uint32_t b[2]) {
    asm volatile(
        "mma.sync.aligned.m16n8k16.row.col.f32.f16.f16.f32 "
        "{%0,%1,%2,%3}, {%4,%5,%6,%7}, {%8,%9}, {%0,%1,%2,%3};\n"
        : "+f"(c[0]), "+f"(c[1]), "+f"(c[2]), "+f"(c[3])
        : "r"(a[0]), "r"(a[1]), "r"(a[2]), "r"(a[3]), "r"(b[0]), "r"(b[1]));
}

// ---------------------------------------------------------------------------
// Preprocessing kernels
// ---------------------------------------------------------------------------
__global__ void f2h_kernel(const float* __restrict__ X, __half* __restrict__ Y,
                           int n4) {
    int i = blockIdx.x * blockDim.x + threadIdx.x;
    if (i < n4) {
        float4 v = ((const float4*)X)[i];
        __half2 h0 = __floats2half2_rn(v.x, v.y);
        __half2 h1 = __floats2half2_rn(v.z, v.w);
        uint2 o;
        o.x = *(uint32_t*)&h0;
        o.y = *(uint32_t*)&h1;
        ((uint2*)Y)[i] = o;
    }
}

// Wt[n][k] = (half) W[k][n]
__global__ void wt_kernel(const float* __restrict__ W, __half* __restrict__ Wt,
                          int K, int N) {
    __shared__ float t[32][33];
    const int k0 = blockIdx.x * 32, n0 = blockIdx.y * 32;
    const int tx = threadIdx.x, ty = threadIdx.y;
    #pragma unroll
    for (int i = 0; i < 4; i++)
        t[ty + 8 * i][tx] = W[(size_t)(k0 + ty + 8 * i) * N + n0 + tx];
    __syncthreads();
    #pragma unroll
    for (int i = 0; i < 4; i++)
        Wt[(size_t)(n0 + ty + 8 * i) * K + k0 + tx] = __float2half(t[tx][ty + 8 * i]);
}

// ---------------------------------------------------------------------------
// fp16 GEMM: C[M,N] = act(A[M,K] @ Bt[N,K]^T + bias[N]); fp32 accum.
// CTA 128x128, BK=32, 4 cp.async stages, 256 threads = 8 warps (2x4),
// warp tile 64x32 of m16n8k16 MMAs.
// Smem per stage: A[128][40]h + B[128][40]h = 20480 B; x4 = 81920 B.
// Fragment LDS banks: word (20g+q) -> all 32 distinct (conflict-free).
// ---------------------------------------------------------------------------
#define ASTRH 40
#define STG_HALF (128 * ASTRH * 2)       // 10240 halves
#define STG_BYTES (STG_HALF * 2)         // 20480
#define GEMM_SMEM (4 * STG_BYTES)        // 81920

template <int ACT, int W32, int W16>
__global__ __launch_bounds__(256, 2) void h_gemm(
    const __half* __restrict__ A, const __half* __restrict__ Bt,
    const float* __restrict__ bias, float* __restrict__ C32,
    __half* __restrict__ C16, int N, int K)
{
    extern __shared__ __half sh[];
    const int tid = threadIdx.x;
    const int bx = blockIdx.x, by = blockIdx.y;
    const int wid = tid >> 5, lane = tid & 31;
    const int wm = (wid >> 2) * 64;       // warp row offset
    const int wn = (wid & 3) * 32;        // warp col offset
    const int g  = lane >> 2;             // 0..7
    const int q  = lane & 3;              // 0..3

    const uint32_t sbase = smem_u32(sh);
    // cp.async: 2 A-chunks + 2 B-chunks of 16B per thread per stage.
    // chunk c: row = c>>2 (0..127), kc = c&3 (16B sub-chunk of the 64B row)
    const int c0 = tid * 2;
    const int r0 = c0 >> 2,       kc0 = c0 & 3;
    const int r1 = (c0 + 1) >> 2, kc1 = (c0 + 1) & 3;

    auto issue = [&](int kt) {
        const uint32_t so = (uint32_t)(kt & 3) * STG_BYTES;
        const __half* a0 = A  + (size_t)(by * 128 + r0) * K + kt * 32 + kc0 * 8;
        const __half* a1 = A  + (size_t)(by * 128 + r1) * K + kt * 32 + kc1 * 8;
        const __half* b0 = Bt + (size_t)(bx * 128 + r0) * K + kt * 32 + kc0 * 8;
        const __half* b1 = Bt + (size_t)(bx * 128 + r1) * K + kt * 32 + kc1 * 8;
        cp16(sbase + so +          (uint32_t)r0 * 80u + (uint32_t)kc0 * 16u, a0);
        cp16(sbase + so +          (uint32_t)r1 * 80u + (uint32_t)kc1 * 16u, a1);
        cp16(sbase + so + 10240u + (uint32_t)r0 * 80u + (uint32_t)kc0 * 16u, b0);
        cp16(sbase + so + 10240u + (uint32_t)r1 * 80u + (uint32_t)kc1 * 16u, b1);
        cp_commit();
    };

    float acc[4][4][4];
    #pragma unroll
    for (int mi = 0; mi < 4; mi++)
        #pragma unroll
        for (int nj = 0; nj < 4; nj++)
            #pragma unroll
            for (int r = 0; r < 4; r++) acc[mi][nj][r] = 0.f;

    const int nk = K >> 5;   // BK = 32

    issue(0); issue(1); issue(2);

    for (int kt = 0; kt < nk; ++kt) {
        cp_wait<2>();
        __syncthreads();
        if (kt + 3 < nk) issue(kt + 3);

        const __half* As = sh + (size_t)(kt & 3) * STG_HALF;
        const __half* Bs = As + 128 * ASTRH;

        #pragma unroll
        for (int ks = 0; ks < 2; ++ks) {
            const int k0 = ks * 16;
            uint32_t a[4][4], b[4][2];
            #pragma unroll
            for (int mi = 0; mi < 4; mi++) {
                const int m0 = wm + mi * 16 + g;
                a[mi][0] = *(const uint32_t*)&As[(m0    ) * ASTRH + k0 + 2 * q];
                a[mi][1] = *(const uint32_t*)&As[(m0 + 8) * ASTRH + k0 + 2 * q];
                a[mi][2] = *(const uint32_t*)&As[(m0    ) * ASTRH + k0 + 8 + 2 * q];
                a[mi][3] = *(const uint32_t*)&As[(m0 + 8) * ASTRH + k0 + 8 + 2 * q];
            }
            #pragma unroll
            for (int nj = 0; nj < 4; nj++) {
                const int n0 = wn + nj * 8 + g;
                b[nj][0] = *(const uint32_t*)&Bs[n0 * ASTRH + k0 + 2 * q];
                b[nj][1] = *(const uint32_t*)&Bs[n0 * ASTRH + k0 + 8 + 2 * q];
            }
            #pragma unroll
            for (int mi = 0; mi < 4; mi++)
                #pragma unroll
                for (int nj = 0; nj < 4; nj++)
                    mma_f16(acc[mi][nj], a[mi], b[nj]);
        }
    }

    // ---- epilogue: bias (+ GELU) + store ----
    #pragma unroll
    for (int nj = 0; nj < 4; nj++) {
        const int col = bx * 128 + wn + nj * 8 + 2 * q;
        const float2 bb = *(const float2*)&bias[col];
        #pragma unroll
        for (int mi = 0; mi < 4; mi++) {
            const int row0 = by * 128 + wm + mi * 16 + g;
            float2 o0, o1;
            o0.x = acc[mi][nj][0] + bb.x;
            o0.y = acc[mi][nj][1] + bb.y;
            o1.x = acc[mi][nj][2] + bb.x;
            o1.y = acc[mi][nj][3] + bb.y;
            if (ACT == 1) {
                o0.x = gelu_erf_f(o0.x); o0.y = gelu_erf_f(o0.y);
                o1.x = gelu_erf_f(o1.x); o1.y = gelu_erf_f(o1.y);
            }
            if (W32) {
                *(float2*)&C32[(size_t)row0 * N + col]       = o0;
                *(float2*)&C32[(size_t)(row0 + 8) * N + col] = o1;
            }
            if (W16) {
                __half2 h0 = __floats2half2_rn(o0.x, o0.y);
                __half2 h1 = __floats2half2_rn(o1.x, o1.y);
                *(__half2*)&C16[(size_t)row0 * N + col]       = h0;
                *(__half2*)&C16[(size_t)(row0 + 8) * N + col] = h1;
            }
        }
    }
}

// ---------------------------------------------------------------------------
// Fused attention: grid (S/64, H, B), 256 threads. fp32; emits fp16 ctx.
// ---------------------------------------------------------------------------
#define SC_STRIDE 516
#define QK_STRIDE 68

__global__ __launch_bounds__(256) void attention_kernel(
    const float* __restrict__ Q, const float* __restrict__ K,
    const float* __restrict__ V, const int* __restrict__ mask,
    const float* __restrict__ adj, __half* __restrict__ ctxh)
{
    extern __shared__ float smem[];
    float* sc = smem;                       // 64 * 516
    float* qs = sc + 64 * SC_STRIDE;        // 64 * 68
    float* kv = qs + 64 * QK_STRIDE;        // 64 * 68

    const int t  = threadIdx.x;
    const int qt = blockIdx.x, h = blockIdx.y, b = blockIdx.z;
    const int qbase = b * S_ + qt * 64;

    #pragma unroll
    for (int i = 0; i < 4; i++) {
        int lin = t + i * 256;
        int r = lin >> 4, c4 = (lin & 15) << 2;
        float4 qv = *(const float4*)&Q[(size_t)(qbase + r) * D_ + h * DK_ + c4];
        qv.x *= 0.125f; qv.y *= 0.125f; qv.z *= 0.125f; qv.w *= 0.125f;
        *(float4*)&qs[r * QK_STRIDE + c4] = qv;
    }

    const int qi  = t >> 2;
    const int kj0 = (t & 3) << 4;
    const int qg  = qt * 64 + qi;

    for (int kt = 0; kt < 8; ++kt) {
        __syncthreads();
        #pragma unroll
        for (int i = 0; i < 4; i++) {
            int lin = t + i * 256;
            int r = lin >> 4, c4 = (lin & 15) << 2;
            float4 kk = *(const float4*)&K[(size_t)(b * S_ + kt * 64 + r) * D_ + h * DK_ + c4];
            kv[(c4 + 0) * QK_STRIDE + r] = kk.x;
            kv[(c4 + 1) * QK_STRIDE + r] = kk.y;
            kv[(c4 + 2) * QK_STRIDE + r] = kk.z;
            kv[(c4 + 3) * QK_STRIDE + r] = kk.w;
        }
        __syncthreads();

        float acc[16];
        #pragma unroll
        for (int j = 0; j < 16; j++) acc[j] = 0.f;

        #pragma unroll
        for (int d = 0; d < 64; ++d) {
            float qv = qs[qi * QK_STRIDE + d];
            const float4* kr = (const float4*)&kv[d * QK_STRIDE + kj0];
            float4 k0 = kr[0], k1 = kr[1], k2 = kr[2], k3 = kr[3];
            acc[0]  += qv * k0.x; acc[1]  += qv * k0.y; acc[2]  += qv * k0.z; acc[3]  += qv * k0.w;
            acc[4]  += qv * k1.x; acc[5]  += qv * k1.y; acc[6]  += qv * k1.z; acc[7]  += qv * k1.w;
            acc[8]  += qv * k2.x; acc[9]  += qv * k2.y; acc[10] += qv * k2.z; acc[11] += qv * k2.w;
            acc[12] += qv * k3.x; acc[13] += qv * k3.y; acc[14] += qv * k3.z; acc[15] += qv * k3.w;
        }

        const float* adjr = &adj[((size_t)(b * S_ + qg)) * S_ + kt * 64 + kj0];
        const int*   mr   = &mask[b * S_ + kt * 64 + kj0];
        float*       scr  = &sc[qi * SC_STRIDE + kt * 64 + kj0];
        #pragma unroll
        for (int j = 0; j < 16; j++)
            scr[j] = acc[j] + (float)mr[j] * -1e9f + adjr[j];
    }
    __syncthreads();

    {
        const int warp = t >> 5, lane = t & 31;
        for (int row = warp; row < 64; row += 8) {
            float* r = &sc[row * SC_STRIDE];
            float mx = -3.0e38f;
            #pragma unroll
            for (int i = 0; i < 16; i++) mx = fmaxf(mx, r[lane + 32 * i]);
            #pragma unroll
            for (int o = 16; o; o >>= 1) mx = fmaxf(mx, __shfl_xor_sync(0xffffffffu, mx, o));
            float e[16], sum = 0.f;
            #pragma unroll
            for (int i = 0; i < 16; i++) { e[i] = __expf(r[lane + 32 * i] - mx); sum += e[i]; }
            #pragma unroll
            for (int o = 16; o; o >>= 1) sum += __shfl_xor_sync(0xffffffffu, sum, o);
            const float inv = 1.0f / sum;
            #pragma unroll
            for (int i = 0; i < 16; i++) r[lane + 32 * i] = e[i] * inv;
        }
    }

    const int dc0 = kj0;
    float acc[16];
    #pragma unroll
    for (int j = 0; j < 16; j++) acc[j] = 0.f;

    for (int kt = 0; kt < 8; ++kt) {
        __syncthreads();
        #pragma unroll
        for (int i = 0; i < 4; i++) {
            int lin = t + i * 256;
            int r = lin >> 4, c4 = (lin & 15) << 2;
            float4 vv = *(const float4*)&V[(size_t)(b * S_ + kt * 64 + r) * D_ + h * DK_ + c4];
            *(float4*)&kv[r * QK_STRIDE + c4] = vv;
        }
        __syncthreads();

        #pragma unroll
        for (int kk = 0; kk < 64; ++kk) {
            float p = sc[qi * SC_STRIDE + kt * 64 + kk];
            const float4* vr = (const float4*)&kv[kk * QK_STRIDE + dc0];
            float4 v0 = vr[0], v1 = vr[1], v2 = vr[2], v3 = vr[3];
            acc[0]  += p * v0.x; acc[1]  += p * v0.y; acc[2]  += p * v0.z; acc[3]  += p * v0.w;
            acc[4]  += p * v1.x; acc[5]  += p * v1.y; acc[6]  += p * v1.z; acc[7]  += p * v1.w;
            acc[8]  += p * v2.x; acc[9]  += p * v2.y; acc[10] += p * v2.z; acc[11] += p * v2.w;
            acc[12] += p * v3.x; acc[13] += p * v3.y; acc[14] += p * v3.z; acc[15] += p * v3.w;
        }
    }

    __half* outp = &ctxh[(size_t)(qbase + qi) * D_ + h * DK_ + dc0];
    #pragma unroll
    for (int j = 0; j < 16; j += 2)
        *(__half2*)&outp[j] = __floats2half2_rn(acc[j], acc[j + 1]);
}

// ---------------------------------------------------------------------------
// Residual + LayerNorm; optional fp16 secondary output
// ---------------------------------------------------------------------------
__device__ __forceinline__ float blockReduceSum(float val, float* shared) {
    const int lane = threadIdx.x & 31, wid = threadIdx.x >> 5;
    #pragma unroll
    for (int o = 16; o; o >>= 1) val += __shfl_xor_sync(0xffffffffu, val, o);
    __syncthreads();
    if (lane == 0) shared[wid] = val;
    __syncthreads();
    float r = shared[0];
    #pragma unroll
    for (int w = 1; w < 8; w++) r += shared[w];
    return r;
}

template <int W16>
__global__ __launch_bounds__(256) void ln_residual_kernel(
    const float* __restrict__ A, const float* __restrict__ Bm,
    const float* __restrict__ gamma, const float* __restrict__ beta,
    float* __restrict__ out, __half* __restrict__ out16)
{
    __shared__ float red[8];
    const int row = blockIdx.x;
    const int tid = threadIdx.x;
    const size_t base = (size_t)row * D_;

    float v[4];
    float s = 0.f;
    #pragma unroll
    for (int i = 0; i < 4; i++) {
        int c = tid + 256 * i;
        v[i] = A[base + c] + Bm[base + c];
        s += v[i];
    }
    s = blockReduceSum(s, red);
    const float mean = s * (1.0f / (float)D_);

    float s2 = 0.f;
    #pragma unroll
    for (int i = 0; i < 4; i++) { float d = v[i] - mean; s2 += d * d; }
    s2 = blockReduceSum(s2, red);

    const float stdv = sqrtf(s2 * (1.0f / (float)(D_ - 1)));   // ddof=1
    const float inv  = 1.0f / (stdv + 1e-6f);                  // /(std+eps)

    #pragma unroll
    for (int i = 0; i < 4; i++) {
        int c = tid + 256 * i;
        float o = gamma[c] * (v[i] - mean) * inv + beta[c];
        out[base + c] = o;
        if (W16) out16[base + c] = __float2half(o);
    }
}

// ---------------------------------------------------------------------------
// launch
// ---------------------------------------------------------------------------
extern "C" void kernel_launch(void* const* d_in, const int* in_sizes, int n_in,
                              void* d_out, int out_size)
{
    const float* x    = (const float*)d_in[0];
    const int*   mask = (const int*)  d_in[1];
    const float* adj  = (const float*)d_in[2];
    const float* Wq = (const float*)d_in[4];  const float* bq = (const float*)d_in[5];
    const float* Wk = (const float*)d_in[6];  const float* bk = (const float*)d_in[7];
    const float* Wv = (const float*)d_in[8];  const float* bv = (const float*)d_in[9];
    const float* Wo = (const float*)d_in[10]; const float* bo = (const float*)d_in[11];
    const float* W1 = (const float*)d_in[12]; const float* b1 = (const float*)d_in[13];
    const float* W2 = (const float*)d_in[14]; const float* b2 = (const float*)d_in[15];
    const float* gamma = (const float*)d_in[16];
    const float* beta  = (const float*)d_in[17];
    float* out = (float*)d_out;

    float *q, *k, *v, *attn, *out1, *ffn;
    __half *xh, *ctxh, *o1h, *hbh, *wqh, *wkh, *wvh, *woh, *w1t, *w2t;
    cudaGetSymbolAddress((void**)&q,    g_q);
    cudaGetSymbolAddress((void**)&k,    g_k);
    cudaGetSymbolAddress((void**)&v,    g_v);
    cudaGetSymbolAddress((void**)&attn, g_attn);
    cudaGetSymbolAddress((void**)&out1, g_out1);
    cudaGetSymbolAddress((void**)&ffn,  g_ffn);
    cudaGetSymbolAddress((void**)&xh,   g_xh);
    cudaGetSymbolAddress((void**)&ctxh, g_ctxh);
    cudaGetSymbolAddress((void**)&o1h,  g_o1h);
    cudaGetSymbolAddress((void**)&hbh,  g_hbh);
    cudaGetSymbolAddress((void**)&wqh,  g_wqh);
    cudaGetSymbolAddress((void**)&wkh,  g_wkh);
    cudaGetSymbolAddress((void**)&wvh,  g_wvh);
    cudaGetSymbolAddress((void**)&woh,  g_woh);
    cudaGetSymbolAddress((void**)&w1t,  g_w1t);
    cudaGetSymbolAddress((void**)&w2t,  g_w2t);

    cudaFuncSetAttribute(h_gemm<0,1,0>,
                         cudaFuncAttributeMaxDynamicSharedMemorySize, GEMM_SMEM);
    cudaFuncSetAttribute(h_gemm<1,0,1>,
                         cudaFuncAttributeMaxDynamicSharedMemorySize, GEMM_SMEM);

    const int ATTN_SMEM = (64 * SC_STRIDE + 2 * 64 * QK_STRIDE) * (int)sizeof(float);
    cudaFuncSetAttribute(attention_kernel,
                         cudaFuncAttributeMaxDynamicSharedMemorySize, ATTN_SMEM);

    // ---- preprocessing: fp16 conversions + weight transposes ----
    f2h_kernel<<<(M_ * D_ / 4 + 255) / 256, 256>>>(x, xh, M_ * D_ / 4);
    dim3 tb(32, 8);
    wt_kernel<<<dim3(D_ / 32, D_ / 32), tb>>>(Wq, wqh, D_, D_);
    wt_kernel<<<dim3(D_ / 32, D_ / 32), tb>>>(Wk, wkh, D_, D_);
    wt_kernel<<<dim3(D_ / 32, D_ / 32), tb>>>(Wv, wvh, D_, D_);
    wt_kernel<<<dim3(D_ / 32, D_ / 32), tb>>>(Wo, woh, D_, D_);
    wt_kernel<<<dim3(D_ / 32, F_ / 32), tb>>>(W1, w1t, D_, F_);
    wt_kernel<<<dim3(F_ / 32, D_ / 32), tb>>>(W2, w2t, F_, D_);

    dim3 gD(D_ / 128, M_ / 128);   // (8, 128)
    dim3 gF(F_ / 128, M_ / 128);   // (32, 128)

    // QKV projections
    h_gemm<0,1,0><<<gD, 256, GEMM_SMEM>>>(xh, wqh, bq, q, (__half*)0, D_, D_);
    h_gemm<0,1,0><<<gD, 256, GEMM_SMEM>>>(xh, wkh, bk, k, (__half*)0, D_, D_);
    h_gemm<0,1,0><<<gD, 256, GEMM_SMEM>>>(xh, wvh, bv, v, (__half*)0, D_, D_);

    // attention (fp32 compute, fp16 ctx out)
    dim3 gA(S_ / 64, H_, B_);
    attention_kernel<<<gA, 256, ATTN_SMEM>>>(q, k, v, mask, adj, ctxh);

    // output projection
    h_gemm<0,1,0><<<gD, 256, GEMM_SMEM>>>(ctxh, woh, bo, attn, (__half*)0, D_, D_);

    // LN1: out1 = LN(x + attn), fp32 + fp16
    ln_residual_kernel<1><<<M_, 256>>>(x, attn, gamma, beta, out1, o1h);

    // FFN
    h_gemm<1,0,1><<<gF, 256, GEMM_SMEM>>>(o1h, w1t, b1, (float*)0, hbh, F_, D_);
    h_gemm<0,1,0><<<gD, 256, GEMM_SMEM>>>(hbh, w2t, b2, ffn, (__half*)0, D_, F_);

    // LN2: out = LN(out1 + ffn)
    ln_residual_kernel<0><<<M_, 256>>>(out1, ffn, gamma, beta, out, (__half*)0);
}

// round 9
// speedup vs baseline: 1.3349x; 1.3349x over previous
#include <cuda_runtime.h>
#include <stdint.h>
#include <math.h>

// ---------------------------------------------------------------------------
// EncoderLayer: B=32, S=512, D=1024, H=16, dk=64, F=4096
// Round 9: round-5 tf32 GEMM engine (proven fastest) + rna-prerounded
// operands (restores round-3 accuracy) + 512-thread attention (2x warps).
// ---------------------------------------------------------------------------

#define B_  32
#define S_  512
#define D_  1024
#define H_  16
#define DK_ 64
#define F_  4096
#define M_  (B_ * S_)          // 16384 rows

// -------------------- scratch (device globals; no allocs) ------------------
__device__ float g_q    [M_ * D_];
__device__ float g_k    [M_ * D_];
__device__ float g_v    [M_ * D_];
__device__ float g_ctx  [M_ * D_];   // rounded (feeds Wo GEMM)
__device__ float g_attn [M_ * D_];
__device__ float g_out1 [M_ * D_];
__device__ float g_out1r[M_ * D_];   // rounded (feeds FFN1)
__device__ float g_ffn  [M_ * D_];
__device__ float g_h    [M_ * F_];   // rounded (feeds FFN2)
__device__ float g_xr   [M_ * D_];   // rounded x
__device__ float g_wqr  [D_ * D_];
__device__ float g_wkr  [D_ * D_];
__device__ float g_wvr  [D_ * D_];
__device__ float g_wor  [D_ * D_];
__device__ float g_w1r  [D_ * F_];
__device__ float g_w2r  [F_ * D_];

// ---------------------------------------------------------------------------
// Helpers
// ---------------------------------------------------------------------------
__device__ __forceinline__ float gelu_erf_f(float x) {
    return 0.5f * x * (1.0f + erff(x * 0.70710678118654752f));
}
__device__ __forceinline__ float tf32r(float f) {   // rna-round to tf32, as fp32 bits
    uint32_t u;
    asm("cvt.rna.tf32.f32 %0, %1;" : "=r"(u) : "f"(f));
    return __uint_as_float(u);
}
__device__ __forceinline__ uint32_t smem_u32(const void* p) {
    uint32_t a;
    asm("{ .reg .u64 t; cvta.to.shared.u64 t, %1; cvt.u32.u64 %0, t; }"
        : "=r"(a) : "l"(p));
    return a;
}
__device__ __forceinline__ void cp16(uint32_t s, const void* g) {
    asm volatile("cp.async.cg.shared.global [%0], [%1], 16;" :: "r"(s), "l"(g));
}
__device__ __forceinline__ void cp_commit() {
    asm volatile("cp.async.commit_group;" ::: "memory");
}
template <int N>
__device__ __forceinline__ void cp_wait() {
    asm volatile("cp.async.wait_group %0;" :: "n"(N) : "memory");
}
__device__ __forceinline__ void mma_tf32(float c[4],
                                         uint32_t a0, uint32_t a1, uint32_t a2, uint32_t a3,
                                         uint32_t b0, uint32_t b1) {
    asm volatile(
        "mma.sync.aligned.m16n8k8.row.col.f32.tf32.tf32.f32 "
        "{%0,%1,%2,%3}, {%4,%5,%6,%7}, {%8,%9}, {%0,%1,%2,%3};\n"
        : "+f"(c[0]), "+f"(c[1]), "+f"(c[2]), "+f"(c[3])
        : "r"(a0), "r"(a1), "r"(a2), "r"(a3), "r"(b0), "r"(b1));
}

// ---------------------------------------------------------------------------
// Preprocess: Y = tf32_rna(X), vectorized
// ---------------------------------------------------------------------------
__global__ void rnd_kernel(const float* __restrict__ X, float* __restrict__ Y,
                           int n4) {
    int i = blockIdx.x * blockDim.x + threadIdx.x;
    if (i < n4) {
        float4 v = ((const float4*)X)[i];
        v.x = tf32r(v.x); v.y = tf32r(v.y); v.z = tf32r(v.z); v.w = tf32r(v.w);
        ((float4*)Y)[i] = v;
    }
}

// ---------------------------------------------------------------------------
// tf32 GEMM (round-5 engine): C[M,N] = act(A[M,K] @ W[K,N] + bias[N])
// CTA 128x128, BK=16 per stage, 4 cp.async stages, 256 threads = 8 warps
// (2x4), warp tile 64x32. Operands pre-rounded to tf32 in GMEM.
// ---------------------------------------------------------------------------
#define ASTR 20
#define BSTR 136
#define STG_FLT (128 * ASTR + 16 * BSTR)   // 4736
#define GEMM_SMEM (4 * STG_FLT * 4)        // 75776 bytes

template <int ACT, int ROUND>
__global__ __launch_bounds__(256, 2) void tf32_gemm(
    const float* __restrict__ A, const float* __restrict__ W,
    const float* __restrict__ bias, float* __restrict__ C,
    int N, int K)
{
    extern __shared__ float sm[];

    const int tid = threadIdx.x;
    const int bx = blockIdx.x, by = blockIdx.y;
    const int wid = tid >> 5, lane = tid & 31;
    const int wm = (wid >> 2) * 64;
    const int wn = (wid & 3) * 32;
    const int g  = lane >> 2;
    const int q  = lane & 3;

    const int ar = tid >> 1, ak = (tid & 1) * 8;
    const int bk = tid >> 4, bn = (tid & 15) * 8;
    const float* Ag = A + (size_t)(by * 128 + ar) * K + ak;
    const float* Bg = W + (size_t)bk * N + bx * 128 + bn;

    uint32_t sA0 = smem_u32(sm) + (uint32_t)(ar * ASTR + ak) * 4u;
    uint32_t sB0 = smem_u32(sm) + (uint32_t)(128 * ASTR + bk * BSTR + bn) * 4u;

    auto issue = [&](int kt) {
        const uint32_t so = (uint32_t)(kt & 3) * (STG_FLT * 4u);
        const float* ap = Ag + kt * 16;
        const float* bp = Bg + (size_t)(kt * 16) * N;
        cp16(sA0 + so,      ap);
        cp16(sA0 + so + 16, ap + 4);
        cp16(sB0 + so,      bp);
        cp16(sB0 + so + 16, bp + 4);
        cp_commit();
    };

    float acc[4][4][4];
    #pragma unroll
    for (int mi = 0; mi < 4; mi++)
        #pragma unroll
        for (int nj = 0; nj < 4; nj++)
            #pragma unroll
            for (int r = 0; r < 4; r++) acc[mi][nj][r] = 0.f;

    const int nk = K >> 4;

    issue(0); issue(1); issue(2);

    for (int kt = 0; kt < nk; ++kt) {
        cp_wait<2>();
        __syncthreads();
        if (kt + 3 < nk) issue(kt + 3);

        const uint32_t* As32 = (const uint32_t*)(sm + (kt & 3) * STG_FLT);
        const uint32_t* Bs32 = As32 + 128 * ASTR;

        #pragma unroll
        for (int ks = 0; ks < 2; ++ks) {
            const int k0 = ks * 8;
            uint32_t a[4][4], b[4][2];
            #pragma unroll
            for (int mi = 0; mi < 4; mi++) {
                const int m0 = wm + mi * 16 + g;
                a[mi][0] = As32[(m0    ) * ASTR + k0 + q];
                a[mi][1] = As32[(m0 + 8) * ASTR + k0 + q];
                a[mi][2] = As32[(m0    ) * ASTR + k0 + q + 4];
                a[mi][3] = As32[(m0 + 8) * ASTR + k0 + q + 4];
            }
            #pragma unroll
            for (int nj = 0; nj < 4; nj++) {
                const int n0 = wn + nj * 8 + g;
                b[nj][0] = Bs32[(k0 + q    ) * BSTR + n0];
                b[nj][1] = Bs32[(k0 + q + 4) * BSTR + n0];
            }
            #pragma unroll
            for (int mi = 0; mi < 4; mi++)
                #pragma unroll
                for (int nj = 0; nj < 4; nj++)
                    mma_tf32(acc[mi][nj], a[mi][0], a[mi][1], a[mi][2], a[mi][3],
                             b[nj][0], b[nj][1]);
        }
    }

    // ---- epilogue ----
    #pragma unroll
    for (int nj = 0; nj < 4; nj++) {
        const int col = bx * 128 + wn + nj * 8 + 2 * q;
        const float2 bb = *(const float2*)&bias[col];
        #pragma unroll
        for (int mi = 0; mi < 4; mi++) {
            const int row0 = by * 128 + wm + mi * 16 + g;
            float2 o0, o1;
            o0.x = acc[mi][nj][0] + bb.x;
            o0.y = acc[mi][nj][1] + bb.y;
            o1.x = acc[mi][nj][2] + bb.x;
            o1.y = acc[mi][nj][3] + bb.y;
            if (ACT == 1) {
                o0.x = gelu_erf_f(o0.x); o0.y = gelu_erf_f(o0.y);
                o1.x = gelu_erf_f(o1.x); o1.y = gelu_erf_f(o1.y);
            }
            if (ROUND == 1) {
                o0.x = tf32r(o0.x); o0.y = tf32r(o0.y);
                o1.x = tf32r(o1.x); o1.y = tf32r(o1.y);
            }
            *(float2*)&C[(size_t)row0 * N + col]       = o0;
            *(float2*)&C[(size_t)(row0 + 8) * N + col] = o1;
        }
    }
}

// ---------------------------------------------------------------------------
// Fused attention: grid (S/64, H, B), 512 threads (16 warps).
// smem: scores[64][516] + Qs[64][68] + KV tile[64][68] = 166,912 bytes.
// Emits tf32-rounded ctx (feeds Wo GEMM).
// ---------------------------------------------------------------------------
#define SC_STRIDE 516
#define QK_STRIDE 68

__global__ __launch_bounds__(512) void attention_kernel(
    const float* __restrict__ Q, const float* __restrict__ K,
    const float* __restrict__ V, const int* __restrict__ mask,
    const float* __restrict__ adj, float* __restrict__ ctx)
{
    extern __shared__ float smem[];
    float* sc = smem;                       // 64 * 516
    float* qs = sc + 64 * SC_STRIDE;        // 64 * 68
    float* kv = qs + 64 * QK_STRIDE;        // 64 * 68

    const int t  = threadIdx.x;
    const int qt = blockIdx.x, h = blockIdx.y, b = blockIdx.z;
    const int qbase = b * S_ + qt * 64;

    // load Q tile (64x64), pre-scaled by 1/8
    #pragma unroll
    for (int i = 0; i < 2; i++) {
        int lin = t + i * 512;
        int r = lin >> 4, c4 = (lin & 15) << 2;
        float4 qv = *(const float4*)&Q[(size_t)(qbase + r) * D_ + h * DK_ + c4];
        qv.x *= 0.125f; qv.y *= 0.125f; qv.z *= 0.125f; qv.w *= 0.125f;
        *(float4*)&qs[r * QK_STRIDE + c4] = qv;
    }

    const int qi  = t >> 3;          // 0..63
    const int kj0 = (t & 7) << 3;    // 0,8,..,56
    const int qg  = qt * 64 + qi;

    // ---- phase 1: scores = QK^T/8 + mask*(-1e9) + adj ----
    for (int kt = 0; kt < 8; ++kt) {
        __syncthreads();   // protect kv reuse (also orders qs stores on kt==0)
        #pragma unroll
        for (int i = 0; i < 2; i++) {
            int lin = t + i * 512;
            int r = lin >> 4, c4 = (lin & 15) << 2;
            float4 kk = *(const float4*)&K[(size_t)(b * S_ + kt * 64 + r) * D_ + h * DK_ + c4];
            kv[(c4 + 0) * QK_STRIDE + r] = kk.x;   // transposed: kv[d][kj]
            kv[(c4 + 1) * QK_STRIDE + r] = kk.y;
            kv[(c4 + 2) * QK_STRIDE + r] = kk.z;
            kv[(c4 + 3) * QK_STRIDE + r] = kk.w;
        }
        __syncthreads();

        float acc[8];
        #pragma unroll
        for (int j = 0; j < 8; j++) acc[j] = 0.f;

        #pragma unroll
        for (int d = 0; d < 64; ++d) {
            float qv = qs[qi * QK_STRIDE + d];
            const float4* kr = (const float4*)&kv[d * QK_STRIDE + kj0];
            float4 k0 = kr[0], k1 = kr[1];
            acc[0] += qv * k0.x; acc[1] += qv * k0.y; acc[2] += qv * k0.z; acc[3] += qv * k0.w;
            acc[4] += qv * k1.x; acc[5] += qv * k1.y; acc[6] += qv * k1.z; acc[7] += qv * k1.w;
        }

        const float* adjr = &adj[((size_t)(b * S_ + qg)) * S_ + kt * 64 + kj0];
        const int*   mr   = &mask[b * S_ + kt * 64 + kj0];
        float*       scr  = &sc[qi * SC_STRIDE + kt * 64 + kj0];
        #pragma unroll
        for (int j = 0; j < 8; j++)
            scr[j] = acc[j] + (float)mr[j] * -1e9f + adjr[j];
    }
    __syncthreads();

    // ---- phase 2: softmax (warp per row, 16 warps) ----
    {
        const int warp = t >> 5, lane = t & 31;
        for (int row = warp; row < 64; row += 16) {
            float* r = &sc[row * SC_STRIDE];
            float mx = -3.0e38f;
            #pragma unroll
            for (int i = 0; i < 16; i++) mx = fmaxf(mx, r[lane + 32 * i]);
            #pragma unroll
            for (int o = 16; o; o >>= 1) mx = fmaxf(mx, __shfl_xor_sync(0xffffffffu, mx, o));
            float e[16], sum = 0.f;
            #pragma unroll
            for (int i = 0; i < 16; i++) { e[i] = __expf(r[lane + 32 * i] - mx); sum += e[i]; }
            #pragma unroll
            for (int o = 16; o; o >>= 1) sum += __shfl_xor_sync(0xffffffffu, sum, o);
            const float inv = 1.0f / sum;
            #pragma unroll
            for (int i = 0; i < 16; i++) r[lane + 32 * i] = e[i] * inv;
        }
    }

    // ---- phase 3: ctx = P @ V ----
    const int dc0 = kj0;
    float acc[8];
    #pragma unroll
    for (int j = 0; j < 8; j++) acc[j] = 0.f;

    for (int kt = 0; kt < 8; ++kt) {
        __syncthreads();   // protect kv reuse; also orders softmax on kt==0
        #pragma unroll
        for (int i = 0; i < 2; i++) {
            int lin = t + i * 512;
            int r = lin >> 4, c4 = (lin & 15) << 2;
            float4 vv = *(const float4*)&V[(size_t)(b * S_ + kt * 64 + r) * D_ + h * DK_ + c4];
            *(float4*)&kv[r * QK_STRIDE + c4] = vv;   // row-major: kv[k][d]
        }
        __syncthreads();

        #pragma unroll
        for (int kk = 0; kk < 64; ++kk) {
            float p = sc[qi * SC_STRIDE + kt * 64 + kk];
            const float4* vr = (const float4*)&kv[kk * QK_STRIDE + dc0];
            float4 v0 = vr[0], v1 = vr[1];
            acc[0] += p * v0.x; acc[1] += p * v0.y; acc[2] += p * v0.z; acc[3] += p * v0.w;
            acc[4] += p * v1.x; acc[5] += p * v1.y; acc[6] += p * v1.z; acc[7] += p * v1.w;
        }
    }

    float* outp = &ctx[(size_t)(qbase + qi) * D_ + h * DK_ + dc0];
    float4 o0, o1;
    o0.x = tf32r(acc[0]); o0.y = tf32r(acc[1]); o0.z = tf32r(acc[2]); o0.w = tf32r(acc[3]);
    o1.x = tf32r(acc[4]); o1.y = tf32r(acc[5]); o1.z = tf32r(acc[6]); o1.w = tf32r(acc[7]);
    *(float4*)&outp[0] = o0;
    *(float4*)&outp[4] = o1;
}

// ---------------------------------------------------------------------------
// Residual + LayerNorm; optional tf32-rounded secondary output
// ---------------------------------------------------------------------------
__device__ __forceinline__ float blockReduceSum(float val, float* shared) {
    const int lane = threadIdx.x & 31, wid = threadIdx.x >> 5;
    #pragma unroll
    for (int o = 16; o; o >>= 1) val += __shfl_xor_sync(0xffffffffu, val, o);
    __syncthreads();
    if (lane == 0) shared[wid] = val;
    __syncthreads();
    float r = shared[0];
    #pragma unroll
    for (int w = 1; w < 8; w++) r += shared[w];
    return r;
}

template <int WR>
__global__ __launch_bounds__(256) void ln_residual_kernel(
    const float* __restrict__ A, const float* __restrict__ Bm,
    const float* __restrict__ gamma, const float* __restrict__ beta,
    float* __restrict__ out, float* __restrict__ outR)
{
    __shared__ float red[8];
    const int row = blockIdx.x;
    const int tid = threadIdx.x;
    const size_t base = (size_t)row * D_;

    float v[4];
    float s = 0.f;
    #pragma unroll
    for (int i = 0; i < 4; i++) {
        int c = tid + 256 * i;
        v[i] = A[base + c] + Bm[base + c];
        s += v[i];
    }
    s = blockReduceSum(s, red);
    const float mean = s * (1.0f / (float)D_);

    float s2 = 0.f;
    #pragma unroll
    for (int i = 0; i < 4; i++) { float d = v[i] - mean; s2 += d * d; }
    s2 = blockReduceSum(s2, red);

    const float stdv = sqrtf(s2 * (1.0f / (float)(D_ - 1)));   // ddof=1
    const float inv  = 1.0f / (stdv + 1e-6f);                  // /(std+eps)

    #pragma unroll
    for (int i = 0; i < 4; i++) {
        int c = tid + 256 * i;
        float o = gamma[c] * (v[i] - mean) * inv + beta[c];
        out[base + c] = o;
        if (WR) outR[base + c] = tf32r(o);
    }
}

// ---------------------------------------------------------------------------
// launch
// ---------------------------------------------------------------------------
extern "C" void kernel_launch(void* const* d_in, const int* in_sizes, int n_in,
                              void* d_out, int out_size)
{
    const float* x    = (const float*)d_in[0];
    const int*   mask = (const int*)  d_in[1];
    const float* adj  = (const float*)d_in[2];
    const float* Wq = (const float*)d_in[4];  const float* bq = (const float*)d_in[5];
    const float* Wk = (const float*)d_in[6];  const float* bk = (const float*)d_in[7];
    const float* Wv = (const float*)d_in[8];  const float* bv = (const float*)d_in[9];
    const float* Wo = (const float*)d_in[10]; const float* bo = (const float*)d_in[11];
    const float* W1 = (const float*)d_in[12]; const float* b1 = (const float*)d_in[13];
    const float* W2 = (const float*)d_in[14]; const float* b2 = (const float*)d_in[15];
    const float* gamma = (const float*)d_in[16];
    const float* beta  = (const float*)d_in[17];
    float* out = (float*)d_out;

    float *q, *k, *v, *ctx, *attn, *out1, *out1r, *ffn, *hbuf;
    float *xr, *wqr, *wkr, *wvr, *wor, *w1r, *w2r;
    cudaGetSymbolAddress((void**)&q,     g_q);
    cudaGetSymbolAddress((void**)&k,     g_k);
    cudaGetSymbolAddress((void**)&v,     g_v);
    cudaGetSymbolAddress((void**)&ctx,   g_ctx);
    cudaGetSymbolAddress((void**)&attn,  g_attn);
    cudaGetSymbolAddress((void**)&out1,  g_out1);
    cudaGetSymbolAddress((void**)&out1r, g_out1r);
    cudaGetSymbolAddress((void**)&ffn,   g_ffn);
    cudaGetSymbolAddress((void**)&hbuf,  g_h);
    cudaGetSymbolAddress((void**)&xr,    g_xr);
    cudaGetSymbolAddress((void**)&wqr,   g_wqr);
    cudaGetSymbolAddress((void**)&wkr,   g_wkr);
    cudaGetSymbolAddress((void**)&wvr,   g_wvr);
    cudaGetSymbolAddress((void**)&wor,   g_wor);
    cudaGetSymbolAddress((void**)&w1r,   g_w1r);
    cudaGetSymbolAddress((void**)&w2r,   g_w2r);

    cudaFuncSetAttribute(tf32_gemm<0,0>,
                         cudaFuncAttributeMaxDynamicSharedMemorySize, GEMM_SMEM);
    cudaFuncSetAttribute(tf32_gemm<1,1>,
                         cudaFuncAttributeMaxDynamicSharedMemorySize, GEMM_SMEM);
    cudaFuncSetAttribute(tf32_gemm<0,1>,
                         cudaFuncAttributeMaxDynamicSharedMemorySize, GEMM_SMEM);

    const int ATTN_SMEM = (64 * SC_STRIDE + 2 * 64 * QK_STRIDE) * (int)sizeof(float);
    cudaFuncSetAttribute(attention_kernel,
                         cudaFuncAttributeMaxDynamicSharedMemorySize, ATTN_SMEM);

    // ---- preprocessing: rna-round GEMM operands ----
    rnd_kernel<<<(M_ * D_ / 4 + 255) / 256, 256>>>(x,  xr,  M_ * D_ / 4);
    rnd_kernel<<<(D_ * D_ / 4 + 255) / 256, 256>>>(Wq, wqr, D_ * D_ / 4);
    rnd_kernel<<<(D_ * D_ / 4 + 255) / 256, 256>>>(Wk, wkr, D_ * D_ / 4);
    rnd_kernel<<<(D_ * D_ / 4 + 255) / 256, 256>>>(Wv, wvr, D_ * D_ / 4);
    rnd_kernel<<<(D_ * D_ / 4 + 255) / 256, 256>>>(Wo, wor, D_ * D_ / 4);
    rnd_kernel<<<(D_ * F_ / 4 + 255) / 256, 256>>>(W1, w1r, D_ * F_ / 4);
    rnd_kernel<<<(F_ * D_ / 4 + 255) / 256, 256>>>(W2, w2r, F_ * D_ / 4);

    dim3 gD(D_ / 128, M_ / 128);   // (8, 128)
    dim3 gF(F_ / 128, M_ / 128);   // (32, 128)

    // QKV projections (outputs exact fp32 -> attention)
    tf32_gemm<0,0><<<gD, 256, GEMM_SMEM>>>(xr, wqr, bq, q, D_, D_);
    tf32_gemm<0,0><<<gD, 256, GEMM_SMEM>>>(xr, wkr, bk, k, D_, D_);
    tf32_gemm<0,0><<<gD, 256, GEMM_SMEM>>>(xr, wvr, bv, v, D_, D_);

    // attention (fp32 compute; emits rounded ctx)
    dim3 gA(S_ / 64, H_, B_);
    attention_kernel<<<gA, 512, ATTN_SMEM>>>(q, k, v, mask, adj, ctx);

    // output projection
    tf32_gemm<0,0><<<gD, 256, GEMM_SMEM>>>(ctx, wor, bo, attn, D_, D_);

    // LN1: out1 = LN(x + attn); exact + rounded
    ln_residual_kernel<1><<<M_, 256>>>(x, attn, gamma, beta, out1, out1r);

    // FFN1: gelu(out1r @ W1 + b1), rounded output
    tf32_gemm<1,1><<<gF, 256, GEMM_SMEM>>>(out1r, w1r, b1, hbuf, F_, D_);
    // FFN2
    tf32_gemm<0,0><<<gD, 256, GEMM_SMEM>>>(hbuf, w2r, b2, ffn, D_, F_);

    // LN2: out = LN(out1 + ffn)
    ln_residual_kernel<0><<<M_, 256>>>(out1, ffn, gamma, beta, out, (float*)0);
}